// round 1
// baseline (speedup 1.0000x reference)
#include <cuda_runtime.h>
#include <cuda_bf16.h>
#include <math.h>

#define N_NODES 100000
#define N_EDGES 1600000
#define DIM 128           // in dim == out dim (8 heads * 16)
#define N_HEADS 8
#define CPH 16            // channels per head
#define LEAKY 0.2f
#define EPS 1e-16f

// ---------------- scratch (device globals; no allocation allowed) ----------------
__device__ float g_h[(size_t)N_NODES * DIM];       // x @ W_lin
__device__ float g_alpha_l[(size_t)N_NODES * N_HEADS];
__device__ float g_alpha_r[(size_t)N_NODES * N_HEADS];
__device__ float g_alpha_e[(size_t)N_EDGES * N_HEADS]; // exp(leakyrelu(logit))
__device__ float g_seg_sum[(size_t)N_NODES * N_HEADS];
__device__ float g_agg[(size_t)N_NODES * DIM];

// ---------------- zero scratch ----------------
__global__ void zero_kernel() {
    int gid = blockIdx.x * blockDim.x + threadIdx.x;
    int total = N_NODES * DIM;
    if (gid < total) g_agg[gid] = 0.0f;
    if (gid < N_NODES * N_HEADS) g_seg_sum[gid] = 0.0f;
}

// ---------------- fused dual GEMM: h = x@W_lin (-> g_h), res = x@W_res (-> d_out) --
// BM=128 rows per block, K=128 full, 4 column tiles of 64 (2 for W_lin, 2 for W_res).
// 256 threads; each thread computes 8 rows x 4 cols per tile.
__global__ void gemm_fused_kernel(const float* __restrict__ x,
                                  const float* __restrict__ Wlin,
                                  const float* __restrict__ Wres,
                                  float* __restrict__ out_res) {
    extern __shared__ float smem[];
    float* sx = smem;                 // [128][129]
    float* sw = smem + 128 * 129;     // [128][65]

    const int tid = threadIdx.x;
    const int row0 = blockIdx.x * 128;

    // load x tile (128 rows x 128 cols) as float4
    for (int i = tid; i < 128 * 32; i += 256) {
        int r = i >> 5;          // 0..127
        int c4 = i & 31;         // 0..31
        float4 v = make_float4(0.f, 0.f, 0.f, 0.f);
        int gr = row0 + r;
        if (gr < N_NODES)
            v = *reinterpret_cast<const float4*>(x + (size_t)gr * DIM + c4 * 4);
        float* dst = &sx[r * 129 + c4 * 4];
        dst[0] = v.x; dst[1] = v.y; dst[2] = v.z; dst[3] = v.w;
    }
    __syncthreads();

    const int tx = tid & 15;     // 16 col groups * 4 cols = 64 cols
    const int ty = tid >> 4;     // 16 row groups * 8 rows = 128 rows

    for (int ct = 0; ct < 4; ct++) {
        const float* Wbase = (ct < 2) ? (Wlin + ct * 64) : (Wres + (ct - 2) * 64);
        // load W tile 128 x 64
        for (int i = tid; i < 128 * 16; i += 256) {
            int r = i >> 4;      // k
            int c4 = i & 15;     // 0..15
            float4 v = *reinterpret_cast<const float4*>(Wbase + (size_t)r * DIM + c4 * 4);
            float* dst = &sw[r * 65 + c4 * 4];
            dst[0] = v.x; dst[1] = v.y; dst[2] = v.z; dst[3] = v.w;
        }
        __syncthreads();

        float acc[8][4];
        #pragma unroll
        for (int i = 0; i < 8; i++)
            #pragma unroll
            for (int j = 0; j < 4; j++) acc[i][j] = 0.0f;

        #pragma unroll 4
        for (int k = 0; k < 128; k++) {
            float b0 = sw[k * 65 + tx * 4 + 0];
            float b1 = sw[k * 65 + tx * 4 + 1];
            float b2 = sw[k * 65 + tx * 4 + 2];
            float b3 = sw[k * 65 + tx * 4 + 3];
            #pragma unroll
            for (int i = 0; i < 8; i++) {
                float a = sx[(ty * 8 + i) * 129 + k];
                acc[i][0] = fmaf(a, b0, acc[i][0]);
                acc[i][1] = fmaf(a, b1, acc[i][1]);
                acc[i][2] = fmaf(a, b2, acc[i][2]);
                acc[i][3] = fmaf(a, b3, acc[i][3]);
            }
        }

        // store
        int colbase = (ct & 1) * 64 + tx * 4;
        #pragma unroll
        for (int i = 0; i < 8; i++) {
            int gr = row0 + ty * 8 + i;
            if (gr < N_NODES) {
                float4 v = make_float4(acc[i][0], acc[i][1], acc[i][2], acc[i][3]);
                if (ct < 2)
                    *reinterpret_cast<float4*>(&g_h[(size_t)gr * DIM + colbase]) = v;
                else
                    *reinterpret_cast<float4*>(&out_res[(size_t)gr * DIM + colbase]) = v;
            }
        }
        __syncthreads();
    }
}

// ---------------- per-node attention logits ----------------
// one thread per (node, head)
__global__ void alpha_kernel(const float* __restrict__ att_l,
                             const float* __restrict__ att_r) {
    __shared__ float sal[DIM], sar[DIM];
    if (threadIdx.x < DIM) {
        sal[threadIdx.x] = att_l[threadIdx.x];
        sar[threadIdx.x] = att_r[threadIdx.x];
    }
    __syncthreads();
    int gid = blockIdx.x * blockDim.x + threadIdx.x;
    if (gid >= N_NODES * N_HEADS) return;
    int n = gid >> 3;
    int hh = gid & 7;
    const float* hp = &g_h[(size_t)n * DIM + hh * CPH];
    float al = 0.f, ar = 0.f;
    #pragma unroll
    for (int c = 0; c < CPH; c++) {
        float hv = hp[c];
        al = fmaf(hv, sal[hh * CPH + c], al);
        ar = fmaf(hv, sar[hh * CPH + c], ar);
    }
    g_alpha_l[gid] = al;
    g_alpha_r[gid] = ar;
}

// ---------------- edge pass: exp(leakyrelu(logit)) + segment sum ----------------
// one thread per (edge, head). Softmax max-shift dropped (shift-invariant; logits tiny).
__global__ void edge_softmax_kernel(const int* __restrict__ edge_index) {
    int gid = blockIdx.x * blockDim.x + threadIdx.x;
    if (gid >= N_EDGES * N_HEADS) return;
    int e = gid >> 3;
    int hh = gid & 7;
    int s = edge_index[e];
    int d = edge_index[N_EDGES + e];
    float a = g_alpha_l[s * N_HEADS + hh] + g_alpha_r[d * N_HEADS + hh];
    a = (a > 0.f) ? a : LEAKY * a;
    float ex = expf(a);
    g_alpha_e[gid] = ex;
    atomicAdd(&g_seg_sum[d * N_HEADS + hh], ex);
}

// ---------------- message scatter: one warp per edge ----------------
// lane L handles floats [L*4, L*4+4) of the 128-wide message; head = L/4.
__global__ void scatter_kernel(const int* __restrict__ edge_index) {
    int gwid = (blockIdx.x * blockDim.x + threadIdx.x) >> 5;
    int lane = threadIdx.x & 31;
    if (gwid >= N_EDGES) return;
    int s = edge_index[gwid];
    int d = edge_index[N_EDGES + gwid];

    float coef = 0.f;
    if (lane < N_HEADS) {
        float e = g_alpha_e[(size_t)gwid * N_HEADS + lane];
        float ssum = g_seg_sum[d * N_HEADS + lane];
        coef = e / (ssum + EPS);
    }
    coef = __shfl_sync(0xffffffffu, coef, lane >> 2);

    float4 hv = *reinterpret_cast<const float4*>(&g_h[(size_t)s * DIM + lane * 4]);
    float4 v = make_float4(hv.x * coef, hv.y * coef, hv.z * coef, hv.w * coef);
    float* addr = &g_agg[(size_t)d * DIM + lane * 4];
    asm volatile("red.global.add.v4.f32 [%0], {%1, %2, %3, %4};"
                 :: "l"(addr), "f"(v.x), "f"(v.y), "f"(v.z), "f"(v.w)
                 : "memory");
}

// ---------------- epilogue: out = elu(agg) + res (res already in d_out) --------
__global__ void elu_residual_kernel(float* __restrict__ out) {
    int gid = blockIdx.x * blockDim.x + threadIdx.x;
    if (gid >= N_NODES * DIM) return;
    float a = g_agg[gid];
    float o = (a > 0.f) ? a : expm1f(a);
    out[gid] = o + out[gid];
}

// ---------------- launch ----------------
extern "C" void kernel_launch(void* const* d_in, const int* in_sizes, int n_in,
                              void* d_out, int out_size) {
    const float* x        = (const float*)d_in[0];
    const int*   eidx     = (const int*)d_in[1];
    const float* Wlin     = (const float*)d_in[2];
    const float* att_l    = (const float*)d_in[3];
    const float* att_r    = (const float*)d_in[4];
    const float* Wres     = (const float*)d_in[5];
    float* out = (float*)d_out;

    static bool attr_set = false;
    size_t smem_bytes = (128 * 129 + 128 * 65) * sizeof(float);
    if (!attr_set) {
        cudaFuncSetAttribute(gemm_fused_kernel,
                             cudaFuncAttributeMaxDynamicSharedMemorySize,
                             (int)smem_bytes);
        attr_set = true;
    }

    // 1. zero scratch accumulators
    zero_kernel<<<(N_NODES * DIM + 255) / 256, 256>>>();

    // 2. dual GEMM: g_h = x@W_lin, d_out = x@W_res
    gemm_fused_kernel<<<(N_NODES + 127) / 128, 256, smem_bytes>>>(x, Wlin, Wres, out);

    // 3. per-node logits
    alpha_kernel<<<(N_NODES * N_HEADS + 255) / 256, 256>>>(att_l, att_r);

    // 4. edge softmax numerators + segment sums
    edge_softmax_kernel<<<(N_EDGES * N_HEADS + 255) / 256, 256>>>(eidx);

    // 5. weighted message scatter-add (warp per edge, vectorized reductions)
    scatter_kernel<<<(N_EDGES * 32 + 255) / 256, 256>>>(eidx);

    // 6. out = elu(agg) + residual
    elu_residual_kernel<<<(N_NODES * DIM + 255) / 256, 256>>>(out);
}

// round 3
// speedup vs baseline: 1.8786x; 1.8786x over previous
#include <cuda_runtime.h>
#include <cuda_bf16.h>
#include <math.h>
#include <stdint.h>

#define N_NODES 100000
#define N_EDGES 1600000
#define DIM 128           // in dim == out dim (8 heads * 16)
#define N_HEADS 8
#define LEAKY 0.2f
#define EPS 1e-16f

#define SA_STRIDE 132     // floats; 132%32=4 -> frag loads conflict-free, float4-aligned
#define SB_STRIDE 133     // floats; 133%32=5 -> transpose store conflict-free
#define SCAN_THREADS 1024
#define NBLK_SCAN 98      // ceil(100000/1024)

// ---------------- scratch (device globals; no allocation allowed) ----------------
__device__ float g_h[(size_t)N_NODES * DIM];            // x @ W_lin (tf32 mma)
__device__ float g_alpha_l[N_NODES * N_HEADS];
__device__ float g_alpha_r[N_NODES * N_HEADS];
__device__ int   g_deg[N_NODES];
__device__ int   g_row[N_NODES + 1];
__device__ int   g_cursor[N_NODES];
__device__ int   g_csr_src[N_EDGES];
__device__ int   g_partial[NBLK_SCAN];

// ============================ CSR build =====================================
__global__ void zero_deg_kernel() {
    int gid = blockIdx.x * blockDim.x + threadIdx.x;
    if (gid < N_NODES) g_deg[gid] = 0;
}

__global__ void hist_kernel(const int* __restrict__ eidx) {
    int gid = blockIdx.x * blockDim.x + threadIdx.x;
    if (gid < N_EDGES) atomicAdd(&g_deg[eidx[N_EDGES + gid]], 1);
}

// block-local exclusive scan of g_deg -> g_row (pre-offset), block sums -> g_partial
__global__ void scan_local_kernel() {
    __shared__ int warp_sums[32];
    int gid = blockIdx.x * SCAN_THREADS + threadIdx.x;
    int v = (gid < N_NODES) ? g_deg[gid] : 0;
    int x = v;
    int lane = threadIdx.x & 31;
    #pragma unroll
    for (int o = 1; o < 32; o <<= 1) {
        int y = __shfl_up_sync(0xffffffffu, x, o);
        if (lane >= o) x += y;
    }
    if (lane == 31) warp_sums[threadIdx.x >> 5] = x;
    __syncthreads();
    if (threadIdx.x < 32) {
        int w = warp_sums[threadIdx.x];
        #pragma unroll
        for (int o = 1; o < 32; o <<= 1) {
            int y = __shfl_up_sync(0xffffffffu, w, o);
            if (threadIdx.x >= o) w += y;
        }
        warp_sums[threadIdx.x] = w;
    }
    __syncthreads();
    int base = (threadIdx.x >= 32) ? warp_sums[(threadIdx.x >> 5) - 1] : 0;
    int incl = x + base;
    if (gid < N_NODES) g_row[gid] = incl - v;      // exclusive
    if (threadIdx.x == SCAN_THREADS - 1) g_partial[blockIdx.x] = incl;
}

__global__ void scan_partials_kernel() {
    if (threadIdx.x == 0 && blockIdx.x == 0) {
        int s = 0;
        for (int i = 0; i < NBLK_SCAN; i++) { int t = g_partial[i]; g_partial[i] = s; s += t; }
    }
}

__global__ void add_offsets_kernel() {
    int gid = blockIdx.x * SCAN_THREADS + threadIdx.x;
    if (gid < N_NODES) {
        int r = g_row[gid] + g_partial[blockIdx.x];
        g_row[gid] = r;
        g_cursor[gid] = r;
    }
    if (gid == 0) g_row[N_NODES] = N_EDGES;
}

__global__ void place_kernel(const int* __restrict__ eidx) {
    int gid = blockIdx.x * blockDim.x + threadIdx.x;
    if (gid < N_EDGES) {
        int d = eidx[N_EDGES + gid];
        int pos = atomicAdd(&g_cursor[d], 1);
        g_csr_src[pos] = eidx[gid];
    }
}

// ======================= tf32 tensor-core dual GEMM =========================
// C = x[100000x128] @ W[128x128]; blockIdx.y: 0 -> W_lin -> g_h, 1 -> W_res -> d_out
__device__ __forceinline__ uint32_t f2tf32(float f) {
    uint32_t r;
    asm("cvt.rna.tf32.f32 %0, %1;" : "=r"(r) : "f"(f));
    return r;
}

__global__ void __launch_bounds__(256, 1)
gemm_tf32_kernel(const float* __restrict__ x,
                 const float* __restrict__ Wlin,
                 const float* __restrict__ Wres,
                 float* __restrict__ out_res) {
    extern __shared__ uint32_t smem_u[];
    uint32_t* sA = smem_u;                       // [128][SA_STRIDE] row-major (m,k)
    uint32_t* sB = smem_u + 128 * SA_STRIDE;     // [128][SB_STRIDE] (n,k) transposed

    const int tid = threadIdx.x;
    const int row0 = blockIdx.x * 128;

    // load A tile (tf32-converted)
    for (int i = tid; i < 128 * 32; i += 256) {
        int r = i >> 5, c4 = i & 31;
        float4 v = make_float4(0.f, 0.f, 0.f, 0.f);
        if (row0 + r < N_NODES)
            v = *reinterpret_cast<const float4*>(x + (size_t)(row0 + r) * DIM + c4 * 4);
        uint4 u;
        u.x = f2tf32(v.x); u.y = f2tf32(v.y); u.z = f2tf32(v.z); u.w = f2tf32(v.w);
        *reinterpret_cast<uint4*>(sA + r * SA_STRIDE + c4 * 4) = u;
    }
    // load W tile transposed: sB[n][k]
    const float* W = blockIdx.y ? Wres : Wlin;
    for (int i = tid; i < 128 * 128; i += 256) {
        int k = i >> 7, n = i & 127;              // consecutive n -> coalesced gmem
        sB[n * SB_STRIDE + k] = f2tf32(W[k * DIM + n]);
    }
    __syncthreads();

    const int warp = tid >> 5, lane = tid & 31;
    const int wm = warp >> 1, wn = warp & 1;      // warp tile: 32 rows x 64 cols
    const int g = lane >> 2, tig = lane & 3;

    float acc[2][8][4];
    #pragma unroll
    for (int i = 0; i < 2; i++)
        #pragma unroll
        for (int j = 0; j < 8; j++)
            #pragma unroll
            for (int c = 0; c < 4; c++) acc[i][j][c] = 0.f;

    #pragma unroll
    for (int ks = 0; ks < 16; ks++) {
        const int k0 = ks * 8;
        uint32_t bf0[8], bf1[8];
        #pragma unroll
        for (int j = 0; j < 8; j++) {
            int n = wn * 64 + j * 8 + g;
            bf0[j] = sB[n * SB_STRIDE + k0 + tig];
            bf1[j] = sB[n * SB_STRIDE + k0 + 4 + tig];
        }
        #pragma unroll
        for (int i = 0; i < 2; i++) {
            int m = wm * 32 + i * 16;
            uint32_t a0 = sA[(m + g) * SA_STRIDE + k0 + tig];
            uint32_t a1 = sA[(m + 8 + g) * SA_STRIDE + k0 + tig];
            uint32_t a2 = sA[(m + g) * SA_STRIDE + k0 + 4 + tig];
            uint32_t a3 = sA[(m + 8 + g) * SA_STRIDE + k0 + 4 + tig];
            #pragma unroll
            for (int j = 0; j < 8; j++) {
                asm volatile(
                    "mma.sync.aligned.m16n8k8.row.col.f32.tf32.tf32.f32 "
                    "{%0,%1,%2,%3}, {%4,%5,%6,%7}, {%8,%9}, {%0,%1,%2,%3};"
                    : "+f"(acc[i][j][0]), "+f"(acc[i][j][1]),
                      "+f"(acc[i][j][2]), "+f"(acc[i][j][3])
                    : "r"(a0), "r"(a1), "r"(a2), "r"(a3),
                      "r"(bf0[j]), "r"(bf1[j]));
            }
        }
    }

    float* outp = blockIdx.y ? out_res : g_h;
    #pragma unroll
    for (int i = 0; i < 2; i++) {
        #pragma unroll
        for (int j = 0; j < 8; j++) {
            int col = wn * 64 + j * 8 + tig * 2;
            int r0 = row0 + wm * 32 + i * 16 + g;
            if (r0 < N_NODES)
                *reinterpret_cast<float2*>(outp + (size_t)r0 * DIM + col) =
                    make_float2(acc[i][j][0], acc[i][j][1]);
            int r1 = r0 + 8;
            if (r1 < N_NODES)
                *reinterpret_cast<float2*>(outp + (size_t)r1 * DIM + col) =
                    make_float2(acc[i][j][2], acc[i][j][3]);
        }
    }
}

// ======================= per-node attention logits ==========================
__global__ void alpha_kernel(const float* __restrict__ att_l,
                             const float* __restrict__ att_r) {
    __shared__ float sal[DIM], sar[DIM];
    if (threadIdx.x < DIM) {
        sal[threadIdx.x] = att_l[threadIdx.x];
        sar[threadIdx.x] = att_r[threadIdx.x];
    }
    __syncthreads();
    int gid = blockIdx.x * blockDim.x + threadIdx.x;
    if (gid >= N_NODES * N_HEADS) return;
    int n = gid >> 3;
    int hh = gid & 7;
    const float* hp = &g_h[(size_t)n * DIM + hh * 16];
    float al = 0.f, ar = 0.f;
    #pragma unroll
    for (int c = 0; c < 16; c++) {
        float hv = hp[c];
        al = fmaf(hv, sal[hh * 16 + c], al);
        ar = fmaf(hv, sar[hh * 16 + c], ar);
    }
    g_alpha_l[gid] = al;
    g_alpha_r[gid] = ar;
}

// =================== fused softmax + gather + ELU + residual ================
// one warp per destination node; no atomics anywhere.
__global__ void aggregate_kernel(float* __restrict__ out) {
    int wid_g = (blockIdx.x * blockDim.x + threadIdx.x) >> 5;
    int lane = threadIdx.x & 31;
    if (wid_g >= N_NODES) return;
    const int dst = wid_g;
    const int beg = g_row[dst], end = g_row[dst + 1];

    float ar = (lane < N_HEADS) ? g_alpha_r[dst * N_HEADS + lane] : 0.f;

    // pass 1: per-head denominator. 4 edges x 8 heads per iteration.
    const int sub = lane >> 3;          // 0..3 : which of 4 parallel edges
    const int h = lane & 7;             // head
    const float arh1 = __shfl_sync(0xffffffffu, ar, h);
    float hsum = 0.f;
    for (int e = beg + sub; e < end; e += 4) {
        int s = g_csr_src[e];
        float a = g_alpha_l[s * N_HEADS + h] + arh1;
        a = (a > 0.f) ? a : LEAKY * a;
        hsum += __expf(a);
    }
    hsum += __shfl_xor_sync(0xffffffffu, hsum, 8);
    hsum += __shfl_xor_sync(0xffffffffu, hsum, 16);   // lane L: sum for head L&7
    float inv = 1.f / (hsum + EPS);
    const int head = lane >> 2;                        // head owning this float4
    const float invh = __shfl_sync(0xffffffffu, inv, head);
    const float arh2 = __shfl_sync(0xffffffffu, ar, head);

    // pass 2: weighted gather of h[src], 2-way ILP
    float4 acc = make_float4(0.f, 0.f, 0.f, 0.f);
    float4 acc2 = make_float4(0.f, 0.f, 0.f, 0.f);
    int e = beg;
    for (; e + 1 < end; e += 2) {
        int s0 = g_csr_src[e];
        int s1 = g_csr_src[e + 1];
        float a0 = g_alpha_l[s0 * N_HEADS + head] + arh2;
        float a1 = g_alpha_l[s1 * N_HEADS + head] + arh2;
        a0 = (a0 > 0.f) ? a0 : LEAKY * a0;
        a1 = (a1 > 0.f) ? a1 : LEAKY * a1;
        float c0 = __expf(a0) * invh;
        float c1 = __expf(a1) * invh;
        float4 h0 = *reinterpret_cast<const float4*>(&g_h[(size_t)s0 * DIM + lane * 4]);
        float4 h1 = *reinterpret_cast<const float4*>(&g_h[(size_t)s1 * DIM + lane * 4]);
        acc.x = fmaf(h0.x, c0, acc.x);  acc.y = fmaf(h0.y, c0, acc.y);
        acc.z = fmaf(h0.z, c0, acc.z);  acc.w = fmaf(h0.w, c0, acc.w);
        acc2.x = fmaf(h1.x, c1, acc2.x); acc2.y = fmaf(h1.y, c1, acc2.y);
        acc2.z = fmaf(h1.z, c1, acc2.z); acc2.w = fmaf(h1.w, c1, acc2.w);
    }
    if (e < end) {
        int s = g_csr_src[e];
        float a = g_alpha_l[s * N_HEADS + head] + arh2;
        a = (a > 0.f) ? a : LEAKY * a;
        float coef = __expf(a) * invh;
        float4 hv = *reinterpret_cast<const float4*>(&g_h[(size_t)s * DIM + lane * 4]);
        acc.x = fmaf(hv.x, coef, acc.x);  acc.y = fmaf(hv.y, coef, acc.y);
        acc.z = fmaf(hv.z, coef, acc.z);  acc.w = fmaf(hv.w, coef, acc.w);
    }
    acc.x += acc2.x; acc.y += acc2.y; acc.z += acc2.z; acc.w += acc2.w;

    float* op = out + (size_t)dst * DIM + lane * 4;
    float4 r = *reinterpret_cast<float4*>(op);         // residual (x @ W_res)
    float4 o;
    o.x = ((acc.x > 0.f) ? acc.x : expm1f(acc.x)) + r.x;
    o.y = ((acc.y > 0.f) ? acc.y : expm1f(acc.y)) + r.y;
    o.z = ((acc.z > 0.f) ? acc.z : expm1f(acc.z)) + r.z;
    o.w = ((acc.w > 0.f) ? acc.w : expm1f(acc.w)) + r.w;
    *reinterpret_cast<float4*>(op) = o;
}

// ================================ launch ====================================
extern "C" void kernel_launch(void* const* d_in, const int* in_sizes, int n_in,
                              void* d_out, int out_size) {
    const float* x     = (const float*)d_in[0];
    const int*   eidx  = (const int*)d_in[1];
    const float* Wlin  = (const float*)d_in[2];
    const float* att_l = (const float*)d_in[3];
    const float* att_r = (const float*)d_in[4];
    const float* Wres  = (const float*)d_in[5];
    float* out = (float*)d_out;

    static bool attr_set = false;
    const size_t smem_bytes = (128 * SA_STRIDE + 128 * SB_STRIDE) * sizeof(uint32_t);
    if (!attr_set) {
        cudaFuncSetAttribute(gemm_tf32_kernel,
                             cudaFuncAttributeMaxDynamicSharedMemorySize, (int)smem_bytes);
        attr_set = true;
    }

    // CSR build (by destination)
    zero_deg_kernel<<<(N_NODES + 255) / 256, 256>>>();
    hist_kernel<<<(N_EDGES + 255) / 256, 256>>>(eidx);
    scan_local_kernel<<<NBLK_SCAN, SCAN_THREADS>>>();
    scan_partials_kernel<<<1, 32>>>();
    add_offsets_kernel<<<NBLK_SCAN, SCAN_THREADS>>>();
    place_kernel<<<(N_EDGES + 255) / 256, 256>>>(eidx);

    // dual GEMM: y=0 -> g_h = x@W_lin ; y=1 -> d_out = x@W_res
    dim3 ggrid((N_NODES + 127) / 128, 2);
    gemm_tf32_kernel<<<ggrid, 256, smem_bytes>>>(x, Wlin, Wres, out);

    // per-node logits
    alpha_kernel<<<(N_NODES * N_HEADS + 255) / 256, 256>>>(att_l, att_r);

    // fused softmax + gather + ELU + residual (warp per dst)
    aggregate_kernel<<<(N_NODES * 32 + 255) / 256, 256>>>(out);
}

// round 4
// speedup vs baseline: 1.9871x; 1.0578x over previous
#include <cuda_runtime.h>
#include <cuda_bf16.h>
#include <math.h>
#include <stdint.h>

#define N_NODES 100000
#define N_EDGES 1600000
#define DIM 128           // in dim == out dim (8 heads * 16)
#define N_HEADS 8
#define LEAKY 0.2f
#define EPS 1e-16f

#define SA_STRIDE 132     // floats; 132%32=4 -> frag loads conflict-free, float4-aligned
#define SB_STRIDE 133     // floats; 133%32=5 -> transpose store conflict-free
#define SCAN_THREADS 1024
#define NBLK_SCAN 98      // ceil(100000/1024)
#define CACHE_E 64        // cached edges per warp in aggregate (max deg ~45 for Poisson(16))

// ---------------- scratch (device globals; no allocation allowed) ----------------
__device__ float g_h[(size_t)N_NODES * DIM];            // x @ W_lin (tf32 mma)
__device__ float g_alpha_l[N_NODES * N_HEADS];
__device__ float g_alpha_r[N_NODES * N_HEADS];
__device__ int   g_deg[N_NODES];
__device__ int   g_row[N_NODES + 1];
__device__ int   g_cursor[N_NODES];
__device__ int   g_csr_src[N_EDGES];
__device__ int   g_partial[NBLK_SCAN];

// ---------------- streams/events: created pre-main (static ctor), never during
// capture or during the harness's mem-checkpointed phases -----------------------
static cudaStream_t s_side = 0;
static cudaEvent_t  ev_fork = 0, ev_join = 0;
static bool s_ok = false;
namespace {
struct StreamInit {
    StreamInit() {
        s_ok = (cudaStreamCreateWithFlags(&s_side, cudaStreamNonBlocking) == cudaSuccess)
            && (cudaEventCreateWithFlags(&ev_fork, cudaEventDisableTiming) == cudaSuccess)
            && (cudaEventCreateWithFlags(&ev_join, cudaEventDisableTiming) == cudaSuccess);
    }
} s_stream_init;
}

// ============================ CSR build =====================================
__global__ void zero_deg_kernel() {
    int gid = blockIdx.x * blockDim.x + threadIdx.x;
    if (gid < N_NODES) g_deg[gid] = 0;
}

__global__ void hist_kernel(const int* __restrict__ eidx) {
    int gid = blockIdx.x * blockDim.x + threadIdx.x;
    if (gid < N_EDGES) atomicAdd(&g_deg[eidx[N_EDGES + gid]], 1);
}

// block-local exclusive scan of g_deg -> g_row (pre-offset), block sums -> g_partial
__global__ void scan_local_kernel() {
    __shared__ int warp_sums[32];
    int gid = blockIdx.x * SCAN_THREADS + threadIdx.x;
    int v = (gid < N_NODES) ? g_deg[gid] : 0;
    int x = v;
    int lane = threadIdx.x & 31;
    #pragma unroll
    for (int o = 1; o < 32; o <<= 1) {
        int y = __shfl_up_sync(0xffffffffu, x, o);
        if (lane >= o) x += y;
    }
    if (lane == 31) warp_sums[threadIdx.x >> 5] = x;
    __syncthreads();
    if (threadIdx.x < 32) {
        int w = warp_sums[threadIdx.x];
        #pragma unroll
        for (int o = 1; o < 32; o <<= 1) {
            int y = __shfl_up_sync(0xffffffffu, w, o);
            if (threadIdx.x >= o) w += y;
        }
        warp_sums[threadIdx.x] = w;
    }
    __syncthreads();
    int base = (threadIdx.x >= 32) ? warp_sums[(threadIdx.x >> 5) - 1] : 0;
    int incl = x + base;
    if (gid < N_NODES) g_row[gid] = incl - v;      // exclusive
    if (threadIdx.x == SCAN_THREADS - 1) g_partial[blockIdx.x] = incl;
}

// parallel exclusive scan of the 98 block partials (128 threads, 4 warps)
__global__ void scan_partials_kernel() {
    __shared__ int ws[4];
    int tid = threadIdx.x;
    int v = (tid < NBLK_SCAN) ? g_partial[tid] : 0;
    int x = v;
    int lane = tid & 31;
    #pragma unroll
    for (int o = 1; o < 32; o <<= 1) {
        int y = __shfl_up_sync(0xffffffffu, x, o);
        if (lane >= o) x += y;
    }
    if (lane == 31) ws[tid >> 5] = x;
    __syncthreads();
    if (tid < 4) {
        int w = ws[tid];
        #pragma unroll
        for (int o = 1; o < 4; o <<= 1) {
            int y = __shfl_up_sync(0x0000000fu, w, o);
            if (tid >= o) w += y;
        }
        ws[tid] = w;
    }
    __syncthreads();
    int base = (tid >= 32) ? ws[(tid >> 5) - 1] : 0;
    if (tid < NBLK_SCAN) g_partial[tid] = x + base - v;   // exclusive
}

__global__ void add_offsets_kernel() {
    int gid = blockIdx.x * SCAN_THREADS + threadIdx.x;
    if (gid < N_NODES) {
        int r = g_row[gid] + g_partial[blockIdx.x];
        g_row[gid] = r;
        g_cursor[gid] = r;
    }
    if (gid == 0) g_row[N_NODES] = N_EDGES;
}

__global__ void place_kernel(const int* __restrict__ eidx) {
    int gid = blockIdx.x * blockDim.x + threadIdx.x;
    if (gid < N_EDGES) {
        int d = eidx[N_EDGES + gid];
        int pos = atomicAdd(&g_cursor[d], 1);
        g_csr_src[pos] = eidx[gid];
    }
}

// ======================= tf32 tensor-core dual GEMM =========================
__device__ __forceinline__ uint32_t f2tf32(float f) {
    uint32_t r;
    asm("cvt.rna.tf32.f32 %0, %1;" : "=r"(r) : "f"(f));
    return r;
}

__global__ void __launch_bounds__(256, 1)
gemm_tf32_kernel(const float* __restrict__ x,
                 const float* __restrict__ Wlin,
                 const float* __restrict__ Wres,
                 float* __restrict__ out_res) {
    extern __shared__ uint32_t smem_u[];
    uint32_t* sA = smem_u;                       // [128][SA_STRIDE] row-major (m,k)
    uint32_t* sB = smem_u + 128 * SA_STRIDE;     // [128][SB_STRIDE] (n,k) transposed

    const int tid = threadIdx.x;
    const int row0 = blockIdx.x * 128;

    for (int i = tid; i < 128 * 32; i += 256) {
        int r = i >> 5, c4 = i & 31;
        float4 v = make_float4(0.f, 0.f, 0.f, 0.f);
        if (row0 + r < N_NODES)
            v = *reinterpret_cast<const float4*>(x + (size_t)(row0 + r) * DIM + c4 * 4);
        uint4 u;
        u.x = f2tf32(v.x); u.y = f2tf32(v.y); u.z = f2tf32(v.z); u.w = f2tf32(v.w);
        *reinterpret_cast<uint4*>(sA + r * SA_STRIDE + c4 * 4) = u;
    }
    const float* W = blockIdx.y ? Wres : Wlin;
    for (int i = tid; i < 128 * 128; i += 256) {
        int k = i >> 7, n = i & 127;
        sB[n * SB_STRIDE + k] = f2tf32(W[k * DIM + n]);
    }
    __syncthreads();

    const int warp = tid >> 5, lane = tid & 31;
    const int wm = warp >> 1, wn = warp & 1;
    const int g = lane >> 2, tig = lane & 3;

    float acc[2][8][4];
    #pragma unroll
    for (int i = 0; i < 2; i++)
        #pragma unroll
        for (int j = 0; j < 8; j++)
            #pragma unroll
            for (int c = 0; c < 4; c++) acc[i][j][c] = 0.f;

    #pragma unroll
    for (int ks = 0; ks < 16; ks++) {
        const int k0 = ks * 8;
        uint32_t bf0[8], bf1[8];
        #pragma unroll
        for (int j = 0; j < 8; j++) {
            int n = wn * 64 + j * 8 + g;
            bf0[j] = sB[n * SB_STRIDE + k0 + tig];
            bf1[j] = sB[n * SB_STRIDE + k0 + 4 + tig];
        }
        #pragma unroll
        for (int i = 0; i < 2; i++) {
            int m = wm * 32 + i * 16;
            uint32_t a0 = sA[(m + g) * SA_STRIDE + k0 + tig];
            uint32_t a1 = sA[(m + 8 + g) * SA_STRIDE + k0 + tig];
            uint32_t a2 = sA[(m + g) * SA_STRIDE + k0 + 4 + tig];
            uint32_t a3 = sA[(m + 8 + g) * SA_STRIDE + k0 + 4 + tig];
            #pragma unroll
            for (int j = 0; j < 8; j++) {
                asm volatile(
                    "mma.sync.aligned.m16n8k8.row.col.f32.tf32.tf32.f32 "
                    "{%0,%1,%2,%3}, {%4,%5,%6,%7}, {%8,%9}, {%0,%1,%2,%3};"
                    : "+f"(acc[i][j][0]), "+f"(acc[i][j][1]),
                      "+f"(acc[i][j][2]), "+f"(acc[i][j][3])
                    : "r"(a0), "r"(a1), "r"(a2), "r"(a3),
                      "r"(bf0[j]), "r"(bf1[j]));
            }
        }
    }

    float* outp = blockIdx.y ? out_res : g_h;
    #pragma unroll
    for (int i = 0; i < 2; i++) {
        #pragma unroll
        for (int j = 0; j < 8; j++) {
            int col = wn * 64 + j * 8 + tig * 2;
            int r0 = row0 + wm * 32 + i * 16 + g;
            if (r0 < N_NODES)
                *reinterpret_cast<float2*>(outp + (size_t)r0 * DIM + col) =
                    make_float2(acc[i][j][0], acc[i][j][1]);
            int r1 = r0 + 8;
            if (r1 < N_NODES)
                *reinterpret_cast<float2*>(outp + (size_t)r1 * DIM + col) =
                    make_float2(acc[i][j][2], acc[i][j][3]);
        }
    }
}

// ======================= per-node attention logits ==========================
__global__ void alpha_kernel(const float* __restrict__ att_l,
                             const float* __restrict__ att_r) {
    __shared__ float sal[DIM], sar[DIM];
    if (threadIdx.x < DIM) {
        sal[threadIdx.x] = att_l[threadIdx.x];
        sar[threadIdx.x] = att_r[threadIdx.x];
    }
    __syncthreads();
    int gid = blockIdx.x * blockDim.x + threadIdx.x;
    if (gid >= N_NODES * N_HEADS) return;
    int n = gid >> 3;
    int hh = gid & 7;
    const float* hp = &g_h[(size_t)n * DIM + hh * 16];
    float al = 0.f, ar = 0.f;
    #pragma unroll
    for (int c = 0; c < 16; c++) {
        float hv = hp[c];
        al = fmaf(hv, sal[hh * 16 + c], al);
        ar = fmaf(hv, sar[hh * 16 + c], ar);
    }
    g_alpha_l[gid] = al;
    g_alpha_r[gid] = ar;
}

// =================== fused softmax + gather + ELU + residual ================
// one warp per destination node; exp coefs cached in smem from pass 1.
__global__ void __launch_bounds__(256)
aggregate_kernel(float* __restrict__ out) {
    __shared__ int   s_src[8][CACHE_E];
    __shared__ float s_coef[8][CACHE_E][N_HEADS];

    int wid_g = (blockIdx.x * blockDim.x + threadIdx.x) >> 5;
    int lane = threadIdx.x & 31;
    int w = threadIdx.x >> 5;
    if (wid_g >= N_NODES) return;
    const int dst = wid_g;
    const int beg = g_row[dst], end = g_row[dst + 1];
    const int deg = end - beg;

    float ar = (lane < N_HEADS) ? g_alpha_r[dst * N_HEADS + lane] : 0.f;

    // pass 1: per-head exp + denominator. 4 edges x 8 heads per iteration.
    const int sub = lane >> 3;          // which of 4 parallel edges
    const int h = lane & 7;             // head
    const float arh1 = __shfl_sync(0xffffffffu, ar, h);
    float hsum = 0.f;
    for (int e = beg + sub; e < end; e += 4) {
        int s = g_csr_src[e];
        float a = g_alpha_l[s * N_HEADS + h] + arh1;
        a = (a > 0.f) ? a : LEAKY * a;
        float ex = __expf(a);
        hsum += ex;
        int idx = e - beg;
        if (idx < CACHE_E) {
            s_coef[w][idx][h] = ex;
            if (h == 0) s_src[w][idx] = s;
        }
    }
    hsum += __shfl_xor_sync(0xffffffffu, hsum, 8);
    hsum += __shfl_xor_sync(0xffffffffu, hsum, 16);   // lane L: sum for head L&7
    float inv = 1.f / (hsum + EPS);
    const int head = lane >> 2;                        // head owning this float4
    const float invh = __shfl_sync(0xffffffffu, inv, head);
    const float arh2 = __shfl_sync(0xffffffffu, ar, head);
    __syncwarp();

    // pass 2: weighted gather of h[src] using cached coefs, 4-way ILP
    float4 acc0 = make_float4(0.f, 0.f, 0.f, 0.f);
    float4 acc1 = make_float4(0.f, 0.f, 0.f, 0.f);
    int nc = (deg < CACHE_E) ? deg : CACHE_E;
    int idx = 0;
    for (; idx + 3 < nc; idx += 4) {
        int s0 = s_src[w][idx + 0];
        int s1 = s_src[w][idx + 1];
        int s2 = s_src[w][idx + 2];
        int s3 = s_src[w][idx + 3];
        float c0 = s_coef[w][idx + 0][head] * invh;
        float c1 = s_coef[w][idx + 1][head] * invh;
        float c2 = s_coef[w][idx + 2][head] * invh;
        float c3 = s_coef[w][idx + 3][head] * invh;
        float4 h0 = *reinterpret_cast<const float4*>(&g_h[(size_t)s0 * DIM + lane * 4]);
        float4 h1 = *reinterpret_cast<const float4*>(&g_h[(size_t)s1 * DIM + lane * 4]);
        float4 h2 = *reinterpret_cast<const float4*>(&g_h[(size_t)s2 * DIM + lane * 4]);
        float4 h3 = *reinterpret_cast<const float4*>(&g_h[(size_t)s3 * DIM + lane * 4]);
        acc0.x = fmaf(h0.x, c0, acc0.x); acc0.y = fmaf(h0.y, c0, acc0.y);
        acc0.z = fmaf(h0.z, c0, acc0.z); acc0.w = fmaf(h0.w, c0, acc0.w);
        acc1.x = fmaf(h1.x, c1, acc1.x); acc1.y = fmaf(h1.y, c1, acc1.y);
        acc1.z = fmaf(h1.z, c1, acc1.z); acc1.w = fmaf(h1.w, c1, acc1.w);
        acc0.x = fmaf(h2.x, c2, acc0.x); acc0.y = fmaf(h2.y, c2, acc0.y);
        acc0.z = fmaf(h2.z, c2, acc0.z); acc0.w = fmaf(h2.w, c2, acc0.w);
        acc1.x = fmaf(h3.x, c3, acc1.x); acc1.y = fmaf(h3.y, c3, acc1.y);
        acc1.z = fmaf(h3.z, c3, acc1.z); acc1.w = fmaf(h3.w, c3, acc1.w);
    }
    for (; idx < nc; idx++) {
        int s = s_src[w][idx];
        float c = s_coef[w][idx][head] * invh;
        float4 hv = *reinterpret_cast<const float4*>(&g_h[(size_t)s * DIM + lane * 4]);
        acc0.x = fmaf(hv.x, c, acc0.x); acc0.y = fmaf(hv.y, c, acc0.y);
        acc0.z = fmaf(hv.z, c, acc0.z); acc0.w = fmaf(hv.w, c, acc0.w);
    }
    // fallback for deg > CACHE_E (practically never taken)
    for (int e = beg + CACHE_E; e < end; e++) {
        int s = g_csr_src[e];
        float a = g_alpha_l[s * N_HEADS + head] + arh2;
        a = (a > 0.f) ? a : LEAKY * a;
        float c = __expf(a) * invh;
        float4 hv = *reinterpret_cast<const float4*>(&g_h[(size_t)s * DIM + lane * 4]);
        acc0.x = fmaf(hv.x, c, acc0.x); acc0.y = fmaf(hv.y, c, acc0.y);
        acc0.z = fmaf(hv.z, c, acc0.z); acc0.w = fmaf(hv.w, c, acc0.w);
    }
    acc0.x += acc1.x; acc0.y += acc1.y; acc0.z += acc1.z; acc0.w += acc1.w;

    float* op = out + (size_t)dst * DIM + lane * 4;
    float4 r = *reinterpret_cast<float4*>(op);         // residual (x @ W_res)
    float4 o;
    o.x = ((acc0.x > 0.f) ? acc0.x : expm1f(acc0.x)) + r.x;
    o.y = ((acc0.y > 0.f) ? acc0.y : expm1f(acc0.y)) + r.y;
    o.z = ((acc0.z > 0.f) ? acc0.z : expm1f(acc0.z)) + r.z;
    o.w = ((acc0.w > 0.f) ? acc0.w : expm1f(acc0.w)) + r.w;
    *reinterpret_cast<float4*>(op) = o;
}

// ================================ launch ====================================
extern "C" void kernel_launch(void* const* d_in, const int* in_sizes, int n_in,
                              void* d_out, int out_size) {
    const float* x     = (const float*)d_in[0];
    const int*   eidx  = (const int*)d_in[1];
    const float* Wlin  = (const float*)d_in[2];
    const float* att_l = (const float*)d_in[3];
    const float* att_r = (const float*)d_in[4];
    const float* Wres  = (const float*)d_in[5];
    float* out = (float*)d_out;

    static bool attr_set = false;
    const size_t smem_bytes = (128 * SA_STRIDE + 128 * SB_STRIDE) * sizeof(uint32_t);
    if (!attr_set) {
        cudaFuncSetAttribute(gemm_tf32_kernel,
                             cudaFuncAttributeMaxDynamicSharedMemorySize, (int)smem_bytes);
        attr_set = true;
    }

    const bool fork = s_ok;
    cudaStream_t sg = fork ? s_side : (cudaStream_t)0;

    if (fork) {
        cudaEventRecord(ev_fork, 0);
        cudaStreamWaitEvent(sg, ev_fork, 0);
    }

    // side stream: dual GEMM (y=0 -> g_h = x@W_lin ; y=1 -> d_out = x@W_res) + logits
    dim3 ggrid((N_NODES + 127) / 128, 2);
    gemm_tf32_kernel<<<ggrid, 256, smem_bytes, sg>>>(x, Wlin, Wres, out);
    alpha_kernel<<<(N_NODES * N_HEADS + 255) / 256, 256, 0, sg>>>(att_l, att_r);

    // main stream: CSR build (by destination)
    zero_deg_kernel<<<(N_NODES + 255) / 256, 256>>>();
    hist_kernel<<<(N_EDGES + 255) / 256, 256>>>(eidx);
    scan_local_kernel<<<NBLK_SCAN, SCAN_THREADS>>>();
    scan_partials_kernel<<<1, 128>>>();
    add_offsets_kernel<<<NBLK_SCAN, SCAN_THREADS>>>();
    place_kernel<<<(N_EDGES + 255) / 256, 256>>>(eidx);

    if (fork) {
        cudaEventRecord(ev_join, sg);
        cudaStreamWaitEvent(0, ev_join, 0);
    }

    // fused softmax + gather + ELU + residual (warp per dst)
    aggregate_kernel<<<(N_NODES * 32 + 255) / 256, 256>>>(out);
}

// round 6
// speedup vs baseline: 2.0500x; 1.0316x over previous
#include <cuda_runtime.h>
#include <cuda_bf16.h>
#include <math.h>
#include <stdint.h>

#define N_NODES 100000
#define N_EDGES 1600000
#define DIM 128           // in dim == out dim (8 heads * 16)
#define N_HEADS 8
#define LEAKY 0.2f
#define EPS 1e-16f

#define SA_STRIDE 132
#define SB_STRIDE 133
#define SCAN_THREADS 1024
#define NBLK_SCAN 98      // ceil(100000/1024)

// ---------------- scratch (device globals; no allocation allowed) ----------------
__device__ float g_h[(size_t)N_NODES * DIM];            // x @ W_lin (tf32 mma)
__device__ float g_alpha_l[N_NODES * N_HEADS];
__device__ float g_alpha_r[N_NODES * N_HEADS];
__device__ int   g_deg[N_NODES];
__device__ int   g_row[N_NODES + 1];
__device__ int   g_cursor[N_NODES];
__device__ int   g_csr_src[N_EDGES];
__device__ int   g_partial[NBLK_SCAN];

// ---------------- streams/events: created pre-main (static ctor) ----------------
static cudaStream_t s_side = 0;
static cudaEvent_t  ev_fork = 0, ev_join = 0;
static bool s_ok = false;
namespace {
struct StreamInit {
    StreamInit() {
        s_ok = (cudaStreamCreateWithFlags(&s_side, cudaStreamNonBlocking) == cudaSuccess)
            && (cudaEventCreateWithFlags(&ev_fork, cudaEventDisableTiming) == cudaSuccess)
            && (cudaEventCreateWithFlags(&ev_join, cudaEventDisableTiming) == cudaSuccess);
    }
} s_stream_init;
}

// ============================ CSR build =====================================
__global__ void zero_deg_kernel() {
    int gid = blockIdx.x * blockDim.x + threadIdx.x;
    if (gid < N_NODES) g_deg[gid] = 0;
}

// 4 edges per thread (int4)
__global__ void hist_kernel(const int* __restrict__ eidx) {
    int gid = blockIdx.x * blockDim.x + threadIdx.x;
    if (gid < N_EDGES / 4) {
        int4 d4 = reinterpret_cast<const int4*>(eidx + N_EDGES)[gid];
        atomicAdd(&g_deg[d4.x], 1);
        atomicAdd(&g_deg[d4.y], 1);
        atomicAdd(&g_deg[d4.z], 1);
        atomicAdd(&g_deg[d4.w], 1);
    }
}

// block-local exclusive scan of g_deg -> g_row (pre-offset), block sums -> g_partial
__global__ void scan_local_kernel() {
    __shared__ int warp_sums[32];
    int gid = blockIdx.x * SCAN_THREADS + threadIdx.x;
    int v = (gid < N_NODES) ? g_deg[gid] : 0;
    int x = v;
    int lane = threadIdx.x & 31;
    #pragma unroll
    for (int o = 1; o < 32; o <<= 1) {
        int y = __shfl_up_sync(0xffffffffu, x, o);
        if (lane >= o) x += y;
    }
    if (lane == 31) warp_sums[threadIdx.x >> 5] = x;
    __syncthreads();
    if (threadIdx.x < 32) {
        int w = warp_sums[threadIdx.x];
        #pragma unroll
        for (int o = 1; o < 32; o <<= 1) {
            int y = __shfl_up_sync(0xffffffffu, w, o);
            if (threadIdx.x >= o) w += y;
        }
        warp_sums[threadIdx.x] = w;
    }
    __syncthreads();
    int base = (threadIdx.x >= 32) ? warp_sums[(threadIdx.x >> 5) - 1] : 0;
    int incl = x + base;
    if (gid < N_NODES) g_row[gid] = incl - v;      // exclusive
    if (threadIdx.x == SCAN_THREADS - 1) g_partial[blockIdx.x] = incl;
}

// parallel exclusive scan of the 98 block partials
__global__ void scan_partials_kernel() {
    __shared__ int ws[4];
    int tid = threadIdx.x;
    int v = (tid < NBLK_SCAN) ? g_partial[tid] : 0;
    int x = v;
    int lane = tid & 31;
    #pragma unroll
    for (int o = 1; o < 32; o <<= 1) {
        int y = __shfl_up_sync(0xffffffffu, x, o);
        if (lane >= o) x += y;
    }
    if (lane == 31) ws[tid >> 5] = x;
    __syncthreads();
    if (tid < 4) {
        int w = ws[tid];
        #pragma unroll
        for (int o = 1; o < 4; o <<= 1) {
            int y = __shfl_up_sync(0x0000000fu, w, o);
            if (tid >= o) w += y;
        }
        ws[tid] = w;
    }
    __syncthreads();
    int base = (tid >= 32) ? ws[(tid >> 5) - 1] : 0;
    if (tid < NBLK_SCAN) g_partial[tid] = x + base - v;   // exclusive
}

__global__ void add_offsets_kernel() {
    int gid = blockIdx.x * SCAN_THREADS + threadIdx.x;
    if (gid < N_NODES) {
        int r = g_row[gid] + g_partial[blockIdx.x];
        g_row[gid] = r;
        g_cursor[gid] = r;
    }
    if (gid == 0) g_row[N_NODES] = N_EDGES;
}

// 4 edges per thread (int4)
__global__ void place_kernel(const int* __restrict__ eidx) {
    int gid = blockIdx.x * blockDim.x + threadIdx.x;
    if (gid < N_EDGES / 4) {
        int4 s4 = reinterpret_cast<const int4*>(eidx)[gid];
        int4 d4 = reinterpret_cast<const int4*>(eidx + N_EDGES)[gid];
        int p0 = atomicAdd(&g_cursor[d4.x], 1);
        int p1 = atomicAdd(&g_cursor[d4.y], 1);
        int p2 = atomicAdd(&g_cursor[d4.z], 1);
        int p3 = atomicAdd(&g_cursor[d4.w], 1);
        g_csr_src[p0] = s4.x;
        g_csr_src[p1] = s4.y;
        g_csr_src[p2] = s4.z;
        g_csr_src[p3] = s4.w;
    }
}

// ======================= tf32 tensor-core dual GEMM =========================
__device__ __forceinline__ uint32_t f2tf32(float f) {
    uint32_t r;
    asm("cvt.rna.tf32.f32 %0, %1;" : "=r"(r) : "f"(f));
    return r;
}

__global__ void __launch_bounds__(256, 1)
gemm_tf32_kernel(const float* __restrict__ x,
                 const float* __restrict__ Wlin,
                 const float* __restrict__ Wres,
                 float* __restrict__ out_res) {
    extern __shared__ uint32_t smem_u[];
    uint32_t* sA = smem_u;                       // [128][SA_STRIDE]
    uint32_t* sB = smem_u + 128 * SA_STRIDE;     // [128][SB_STRIDE] (n,k)

    const int tid = threadIdx.x;
    const int row0 = blockIdx.x * 128;

    for (int i = tid; i < 128 * 32; i += 256) {
        int r = i >> 5, c4 = i & 31;
        float4 v = make_float4(0.f, 0.f, 0.f, 0.f);
        if (row0 + r < N_NODES)
            v = *reinterpret_cast<const float4*>(x + (size_t)(row0 + r) * DIM + c4 * 4);
        uint4 u;
        u.x = f2tf32(v.x); u.y = f2tf32(v.y); u.z = f2tf32(v.z); u.w = f2tf32(v.w);
        *reinterpret_cast<uint4*>(sA + r * SA_STRIDE + c4 * 4) = u;
    }
    const float* W = blockIdx.y ? Wres : Wlin;
    for (int i = tid; i < 128 * 128; i += 256) {
        int k = i >> 7, n = i & 127;
        sB[n * SB_STRIDE + k] = f2tf32(W[k * DIM + n]);
    }
    __syncthreads();

    const int warp = tid >> 5, lane = tid & 31;
    const int wm = warp >> 1, wn = warp & 1;
    const int g = lane >> 2, tig = lane & 3;

    float acc[2][8][4];
    #pragma unroll
    for (int i = 0; i < 2; i++)
        #pragma unroll
        for (int j = 0; j < 8; j++)
            #pragma unroll
            for (int c = 0; c < 4; c++) acc[i][j][c] = 0.f;

    #pragma unroll
    for (int ks = 0; ks < 16; ks++) {
        const int k0 = ks * 8;
        uint32_t bf0[8], bf1[8];
        #pragma unroll
        for (int j = 0; j < 8; j++) {
            int n = wn * 64 + j * 8 + g;
            bf0[j] = sB[n * SB_STRIDE + k0 + tig];
            bf1[j] = sB[n * SB_STRIDE + k0 + 4 + tig];
        }
        #pragma unroll
        for (int i = 0; i < 2; i++) {
            int m = wm * 32 + i * 16;
            uint32_t a0 = sA[(m + g) * SA_STRIDE + k0 + tig];
            uint32_t a1 = sA[(m + 8 + g) * SA_STRIDE + k0 + tig];
            uint32_t a2 = sA[(m + g) * SA_STRIDE + k0 + 4 + tig];
            uint32_t a3 = sA[(m + 8 + g) * SA_STRIDE + k0 + 4 + tig];
            #pragma unroll
            for (int j = 0; j < 8; j++) {
                asm volatile(
                    "mma.sync.aligned.m16n8k8.row.col.f32.tf32.tf32.f32 "
                    "{%0,%1,%2,%3}, {%4,%5,%6,%7}, {%8,%9}, {%0,%1,%2,%3};"
                    : "+f"(acc[i][j][0]), "+f"(acc[i][j][1]),
                      "+f"(acc[i][j][2]), "+f"(acc[i][j][3])
                    : "r"(a0), "r"(a1), "r"(a2), "r"(a3),
                      "r"(bf0[j]), "r"(bf1[j]));
            }
        }
    }

    float* outp = blockIdx.y ? out_res : g_h;
    #pragma unroll
    for (int i = 0; i < 2; i++) {
        #pragma unroll
        for (int j = 0; j < 8; j++) {
            int col = wn * 64 + j * 8 + tig * 2;
            int r0 = row0 + wm * 32 + i * 16 + g;
            if (r0 < N_NODES)
                *reinterpret_cast<float2*>(outp + (size_t)r0 * DIM + col) =
                    make_float2(acc[i][j][0], acc[i][j][1]);
            int r1 = r0 + 8;
            if (r1 < N_NODES)
                *reinterpret_cast<float2*>(outp + (size_t)r1 * DIM + col) =
                    make_float2(acc[i][j][2], acc[i][j][3]);
        }
    }
}

// ======================= per-node attention logits ==========================
__global__ void alpha_kernel(const float* __restrict__ att_l,
                             const float* __restrict__ att_r) {
    __shared__ float sal[DIM], sar[DIM];
    if (threadIdx.x < DIM) {
        sal[threadIdx.x] = att_l[threadIdx.x];
        sar[threadIdx.x] = att_r[threadIdx.x];
    }
    __syncthreads();
    int gid = blockIdx.x * blockDim.x + threadIdx.x;
    if (gid >= N_NODES * N_HEADS) return;
    int n = gid >> 3;
    int hh = gid & 7;
    const float* hp = &g_h[(size_t)n * DIM + hh * 16];
    float al = 0.f, ar = 0.f;
    #pragma unroll
    for (int c = 0; c < 16; c++) {
        float hv = hp[c];
        al = fmaf(hv, sal[hh * 16 + c], al);
        ar = fmaf(hv, sar[hh * 16 + c], ar);
    }
    g_alpha_l[gid] = al;
    g_alpha_r[gid] = ar;
}

// ============ single-pass fused softmax + gather + ELU + residual ===========
// one warp per destination node. Key identity (no max-shift needed):
//   sum_e coef_e * h[src_e] = (sum_e exp_e * h[src_e]) / (sum_e exp_e + eps)
// so normalization is a single post-scale; ONE edge pass, no smem, no atomics.
__global__ void __launch_bounds__(256)
aggregate_kernel(float* __restrict__ out) {
    int wid_g = (blockIdx.x * blockDim.x + threadIdx.x) >> 5;
    int lane = threadIdx.x & 31;
    if (wid_g >= N_NODES) return;
    const int dst = wid_g;
    const int beg = __ldg(&g_row[dst]);
    const int end = __ldg(&g_row[dst + 1]);
    const int head = lane >> 2;                    // head owning this float4

    const float ar = __ldg(&g_alpha_r[dst * N_HEADS + head]);

    float4 acc0 = make_float4(0.f, 0.f, 0.f, 0.f);
    float4 acc1 = make_float4(0.f, 0.f, 0.f, 0.f);
    float hsum = 0.f;                              // identical across 4 lanes of group

    int e = beg;
    for (; e + 3 < end; e += 4) {
        int s0 = __ldg(&g_csr_src[e + 0]);
        int s1 = __ldg(&g_csr_src[e + 1]);
        int s2 = __ldg(&g_csr_src[e + 2]);
        int s3 = __ldg(&g_csr_src[e + 3]);
        float a0 = __ldg(&g_alpha_l[s0 * N_HEADS + head]) + ar;
        float a1 = __ldg(&g_alpha_l[s1 * N_HEADS + head]) + ar;
        float a2 = __ldg(&g_alpha_l[s2 * N_HEADS + head]) + ar;
        float a3 = __ldg(&g_alpha_l[s3 * N_HEADS + head]) + ar;
        a0 = (a0 > 0.f) ? a0 : LEAKY * a0;
        a1 = (a1 > 0.f) ? a1 : LEAKY * a1;
        a2 = (a2 > 0.f) ? a2 : LEAKY * a2;
        a3 = (a3 > 0.f) ? a3 : LEAKY * a3;
        float x0 = __expf(a0), x1 = __expf(a1), x2 = __expf(a2), x3 = __expf(a3);
        float4 h0 = *reinterpret_cast<const float4*>(&g_h[(size_t)s0 * DIM + lane * 4]);
        float4 h1 = *reinterpret_cast<const float4*>(&g_h[(size_t)s1 * DIM + lane * 4]);
        float4 h2 = *reinterpret_cast<const float4*>(&g_h[(size_t)s2 * DIM + lane * 4]);
        float4 h3 = *reinterpret_cast<const float4*>(&g_h[(size_t)s3 * DIM + lane * 4]);
        hsum += (x0 + x1) + (x2 + x3);
        acc0.x = fmaf(h0.x, x0, acc0.x); acc0.y = fmaf(h0.y, x0, acc0.y);
        acc0.z = fmaf(h0.z, x0, acc0.z); acc0.w = fmaf(h0.w, x0, acc0.w);
        acc1.x = fmaf(h1.x, x1, acc1.x); acc1.y = fmaf(h1.y, x1, acc1.y);
        acc1.z = fmaf(h1.z, x1, acc1.z); acc1.w = fmaf(h1.w, x1, acc1.w);
        acc0.x = fmaf(h2.x, x2, acc0.x); acc0.y = fmaf(h2.y, x2, acc0.y);
        acc0.z = fmaf(h2.z, x2, acc0.z); acc0.w = fmaf(h2.w, x2, acc0.w);
        acc1.x = fmaf(h3.x, x3, acc1.x); acc1.y = fmaf(h3.y, x3, acc1.y);
        acc1.z = fmaf(h3.z, x3, acc1.z); acc1.w = fmaf(h3.w, x3, acc1.w);
    }
    for (; e < end; e++) {
        int s = __ldg(&g_csr_src[e]);
        float a = __ldg(&g_alpha_l[s * N_HEADS + head]) + ar;
        a = (a > 0.f) ? a : LEAKY * a;
        float ex = __expf(a);
        float4 hv = *reinterpret_cast<const float4*>(&g_h[(size_t)s * DIM + lane * 4]);
        hsum += ex;
        acc0.x = fmaf(hv.x, ex, acc0.x); acc0.y = fmaf(hv.y, ex, acc0.y);
        acc0.z = fmaf(hv.z, ex, acc0.z); acc0.w = fmaf(hv.w, ex, acc0.w);
    }

    const float inv = 1.f / (hsum + EPS);
    float4 acc;
    acc.x = (acc0.x + acc1.x) * inv;
    acc.y = (acc0.y + acc1.y) * inv;
    acc.z = (acc0.z + acc1.z) * inv;
    acc.w = (acc0.w + acc1.w) * inv;

    float* op = out + (size_t)dst * DIM + lane * 4;
    float4 r = *reinterpret_cast<float4*>(op);     // residual (x @ W_res)
    float4 o;
    o.x = ((acc.x > 0.f) ? acc.x : expm1f(acc.x)) + r.x;
    o.y = ((acc.y > 0.f) ? acc.y : expm1f(acc.y)) + r.y;
    o.z = ((acc.z > 0.f) ? acc.z : expm1f(acc.z)) + r.z;
    o.w = ((acc.w > 0.f) ? acc.w : expm1f(acc.w)) + r.w;
    *reinterpret_cast<float4*>(op) = o;
}

// ================================ launch ====================================
extern "C" void kernel_launch(void* const* d_in, const int* in_sizes, int n_in,
                              void* d_out, int out_size) {
    const float* x     = (const float*)d_in[0];
    const int*   eidx  = (const int*)d_in[1];
    const float* Wlin  = (const float*)d_in[2];
    const float* att_l = (const float*)d_in[3];
    const float* att_r = (const float*)d_in[4];
    const float* Wres  = (const float*)d_in[5];
    float* out = (float*)d_out;

    static bool attr_set = false;
    const size_t smem_bytes = (128 * SA_STRIDE + 128 * SB_STRIDE) * sizeof(uint32_t);
    if (!attr_set) {
        cudaFuncSetAttribute(gemm_tf32_kernel,
                             cudaFuncAttributeMaxDynamicSharedMemorySize, (int)smem_bytes);
        attr_set = true;
    }

    const bool fork = s_ok;
    cudaStream_t sg = fork ? s_side : (cudaStream_t)0;

    if (fork) {
        cudaEventRecord(ev_fork, 0);
        cudaStreamWaitEvent(sg, ev_fork, 0);
    }

    // side stream: dual GEMM (y=0 -> g_h = x@W_lin ; y=1 -> d_out = x@W_res) + logits
    dim3 ggrid((N_NODES + 127) / 128, 2);
    gemm_tf32_kernel<<<ggrid, 256, smem_bytes, sg>>>(x, Wlin, Wres, out);
    alpha_kernel<<<(N_NODES * N_HEADS + 255) / 256, 256, 0, sg>>>(att_l, att_r);

    // main stream: CSR build (by destination)
    zero_deg_kernel<<<(N_NODES + 255) / 256, 256>>>();
    hist_kernel<<<(N_EDGES / 4 + 255) / 256, 256>>>(eidx);
    scan_local_kernel<<<NBLK_SCAN, SCAN_THREADS>>>();
    scan_partials_kernel<<<1, 128>>>();
    add_offsets_kernel<<<NBLK_SCAN, SCAN_THREADS>>>();
    place_kernel<<<(N_EDGES / 4 + 255) / 256, 256>>>(eidx);

    if (fork) {
        cudaEventRecord(ev_join, sg);
        cudaStreamWaitEvent(0, ev_join, 0);
    }

    // single-pass fused softmax + gather + ELU + residual (warp per dst)
    aggregate_kernel<<<(N_NODES * 32 + 255) / 256, 256>>>(out);
}